// round 3
// baseline (speedup 1.0000x reference)
#include <cuda_runtime.h>
#include <cstdint>

// PatchPermAugmentation: x (B,T,N,C)=(32,1024,512,3) fp32, perm (B, NB=512) int32.
// out[b,t,n,0] = x[b, perm[b,t/2]*2 + t%2, n, 0]; out[b,t,n,1:] = x[b,t,n,1:].
//
// Persistent grid-stride version: 2048 CTAs x 256 threads; each CTA walks
// patch blocks with stride gridDim.x. One patch block = 768 contiguous
// float4 (both rows t=2*blk, 2*blk+1 share one perm entry).
// Identity blocks (majority) are a pure vectorized copy; permuted blocks also
// read the contiguous source block (L2-resident, same 6MB batch slab) and
// select components by (float4 index) % 3:
//   m==0 -> {x,w} from src; m==1 -> {z}; m==2 -> {y}.
// Normal cached stores (R2 showed evict-first stores lose the cross-replay
// L2 carryover and cost ~1us).

#define BB 32
#define TT 1024
#define NN 512
#define PSZ 2
#define NBLK (TT / PSZ)                 // 512
#define ROW_VEC4 ((NN * 3) / 4)         // 384
#define BLK_VEC4 (PSZ * ROW_VEC4)       // 768
#define TOTAL_BLKS (BB * NBLK)          // 16384
#define NCTA 2048

__global__ __launch_bounds__(256)
void patch_perm_kernel(const float4* __restrict__ x,
                       const int* __restrict__ perm,
                       float4* __restrict__ out) {
    const int tid = threadIdx.x;

    for (int gblk = blockIdx.x; gblk < TOTAL_BLKS; gblk += NCTA) {
        const int blk = gblk & (NBLK - 1);
        const int src_blk = perm[gblk];        // perm is (B, NBLK) contiguous

        const size_t base = (size_t)gblk * BLK_VEC4;
        const float4* __restrict__ idr = x + base;
        float4* __restrict__ outr = out + base;

        const int i0 = tid;                    // 0..255
        const int i1 = tid + 256;
        const int i2 = tid + 512;

        // Front-batched identity loads (MLP >= 3)
        float4 v0 = idr[i0];
        float4 v1 = idr[i1];
        float4 v2 = idr[i2];

        if (src_blk != blk) {                  // uniform branch per CTA
            const float4* __restrict__ sr =
                x + ((size_t)(gblk - blk) + src_blk) * BLK_VEC4;
            float4 s0 = sr[i0];
            float4 s1 = sr[i1];
            float4 s2 = sr[i2];

            int m0 = i0 % 3;
            if (m0 == 0)      { v0.x = s0.x; v0.w = s0.w; }
            else if (m0 == 1) { v0.z = s0.z; }
            else              { v0.y = s0.y; }

            int m1 = i1 % 3;
            if (m1 == 0)      { v1.x = s1.x; v1.w = s1.w; }
            else if (m1 == 1) { v1.z = s1.z; }
            else              { v1.y = s1.y; }

            int m2 = i2 % 3;
            if (m2 == 0)      { v2.x = s2.x; v2.w = s2.w; }
            else if (m2 == 1) { v2.z = s2.z; }
            else              { v2.y = s2.y; }
        }

        outr[i0] = v0;
        outr[i1] = v1;
        outr[i2] = v2;
    }
}

extern "C" void kernel_launch(void* const* d_in, const int* in_sizes, int n_in,
                              void* d_out, int out_size) {
    const float4* x = (const float4*)d_in[0];
    const int* perm = (const int*)d_in[1];
    float4* out = (float4*)d_out;

    patch_perm_kernel<<<NCTA, 256>>>(x, perm, out);
}

// round 5
// speedup vs baseline: 1.0598x; 1.0598x over previous
#include <cuda_runtime.h>
#include <cstdint>

// PatchPermAugmentation: x (B,T,N,C)=(32,1024,512,3) fp32, perm (B, NB=512) int32.
// out[b,t,n,0] = x[b, perm[b,t/2]*2 + t%2, n, 0]; out[b,t,n,1:] = x[b,t,n,1:].
//
// R1 structure (best so far: 55.6us kernel, 6.28 TB/s): one CTA per (b,t) row,
// 128 threads x 3 float4, fire-and-exit. Identity rows (majority) are a pure
// vectorized copy; permuted rows also read the source row (L2-resident within
// the 6MB batch slab) and select components by (float4 index) % 3:
//   m==0 -> {x,w} from src; m==1 -> {z}; m==2 -> {y}.
//
// R4 change (isolated): __launch_bounds__(128, 16) caps regs at 32 to lift
// theoretical occupancy from 48 to 64 warps/SM -> deeper memory queues.
// (R2 lesson: keep default cached stores; R3 lesson: no persistent loops.)

#define BB 32
#define TT 1024
#define NN 512
#define PSZ 2
#define NBLK (TT / PSZ)            // 512
#define ROW_VEC4 ((NN * 3) / 4)    // 384

__global__ __launch_bounds__(128, 16)
void patch_perm_kernel(const float4* __restrict__ x,
                       const int* __restrict__ perm,
                       float4* __restrict__ out) {
    const int row = blockIdx.x;          // b*T + t
    const int b = row >> 10;             // row / 1024
    const int t = row & (TT - 1);        // row % 1024
    const int blk = t >> 1;
    const int src_t = perm[b * NBLK + blk] * PSZ + (t & 1);

    const float4* __restrict__ idr = x + (size_t)row * ROW_VEC4;
    float4* __restrict__ outr = out + (size_t)row * ROW_VEC4;

    const int i0 = threadIdx.x;          // 0..127
    const int i1 = i0 + 128;
    const int i2 = i0 + 256;

    // Front-batched identity loads (MLP>=3)
    float4 v0 = idr[i0];
    float4 v1 = idr[i1];
    float4 v2 = idr[i2];

    if (src_t != t) {                    // uniform branch per CTA
        const float4* __restrict__ sr =
            x + (size_t)(b * TT + src_t) * ROW_VEC4;
        float4 s0 = sr[i0];
        float4 s1 = sr[i1];
        float4 s2 = sr[i2];

        // component selection by (float4 index) % 3
        int m0 = i0 % 3;
        if (m0 == 0)      { v0.x = s0.x; v0.w = s0.w; }
        else if (m0 == 1) { v0.z = s0.z; }
        else              { v0.y = s0.y; }

        int m1 = i1 % 3;
        if (m1 == 0)      { v1.x = s1.x; v1.w = s1.w; }
        else if (m1 == 1) { v1.z = s1.z; }
        else              { v1.y = s1.y; }

        int m2 = i2 % 3;
        if (m2 == 0)      { v2.x = s2.x; v2.w = s2.w; }
        else if (m2 == 1) { v2.z = s2.z; }
        else              { v2.y = s2.y; }
    }

    outr[i0] = v0;
    outr[i1] = v1;
    outr[i2] = v2;
}

extern "C" void kernel_launch(void* const* d_in, const int* in_sizes, int n_in,
                              void* d_out, int out_size) {
    const float4* x = (const float4*)d_in[0];
    const int* perm = (const int*)d_in[1];
    float4* out = (float4*)d_out;

    dim3 grid(BB * TT);   // 32768 rows
    dim3 block(128);
    patch_perm_kernel<<<grid, block>>>(x, perm, out);
}

// round 7
// speedup vs baseline: 1.0797x; 1.0188x over previous
#include <cuda_runtime.h>
#include <cstdint>

// PatchPermAugmentation: x (B,T,N,C)=(32,1024,512,3) fp32, perm (B, NB=512) int32.
// out[b,t,n,0] = x[b, perm[b,t/2]*2 + t%2, n, 0]; out[b,t,n,1:] = x[b,t,n,1:].
//
// R1 structure (best: 55.6us kernel, 6.28 TB/s): one CTA per (b,t) row,
// 128 threads x 3 front-batched float4, fire-and-exit. Identity rows
// (majority) are a pure vectorized copy; permuted rows also read the source
// row and select components by (float4 index) % 3:
//   m==0 -> {x,w} from src; m==1 -> {z}; m==2 -> {y}.
//
// Lessons locked in: no __stcs on stores (R2: loses cross-replay L2
// carryover), no persistent loop (R3: serializes MLP), no reg cap (R5: cold
// path spills). This round (re-run of R6 after infra failure): __ldcs on
// src-row loads only — src lines are dead after this read ~half the time, so
// evict-first frees L2 for the input carryover set. Hot path bit-identical
// to R1.

#define BB 32
#define TT 1024
#define NN 512
#define PSZ 2
#define NBLK (TT / PSZ)            // 512
#define ROW_VEC4 ((NN * 3) / 4)    // 384

__global__ __launch_bounds__(128)
void patch_perm_kernel(const float4* __restrict__ x,
                       const int* __restrict__ perm,
                       float4* __restrict__ out) {
    const int row = blockIdx.x;          // b*T + t
    const int b = row >> 10;             // row / 1024
    const int t = row & (TT - 1);        // row % 1024
    const int blk = t >> 1;
    const int src_t = perm[b * NBLK + blk] * PSZ + (t & 1);

    const float4* __restrict__ idr = x + (size_t)row * ROW_VEC4;
    float4* __restrict__ outr = out + (size_t)row * ROW_VEC4;

    const int i0 = threadIdx.x;          // 0..127
    const int i1 = i0 + 128;
    const int i2 = i0 + 256;

    // Front-batched identity loads (MLP>=3)
    float4 v0 = idr[i0];
    float4 v1 = idr[i1];
    float4 v2 = idr[i2];

    if (src_t != t) {                    // uniform branch per CTA (~13-25%)
        const float4* __restrict__ sr =
            x + (size_t)(b * TT + src_t) * ROW_VEC4;
        // Evict-first: these lines are not re-read after this point
        // (each selected row is read once as id, once as src).
        float4 s0 = __ldcs(sr + i0);
        float4 s1 = __ldcs(sr + i1);
        float4 s2 = __ldcs(sr + i2);

        // component selection by (float4 index) % 3
        int m0 = i0 % 3;
        if (m0 == 0)      { v0.x = s0.x; v0.w = s0.w; }
        else if (m0 == 1) { v0.z = s0.z; }
        else              { v0.y = s0.y; }

        int m1 = i1 % 3;
        if (m1 == 0)      { v1.x = s1.x; v1.w = s1.w; }
        else if (m1 == 1) { v1.z = s1.z; }
        else              { v1.y = s1.y; }

        int m2 = i2 % 3;
        if (m2 == 0)      { v2.x = s2.x; v2.w = s2.w; }
        else if (m2 == 1) { v2.z = s2.z; }
        else              { v2.y = s2.y; }
    }

    outr[i0] = v0;
    outr[i1] = v1;
    outr[i2] = v2;
}

extern "C" void kernel_launch(void* const* d_in, const int* in_sizes, int n_in,
                              void* d_out, int out_size) {
    const float4* x = (const float4*)d_in[0];
    const int* perm = (const int*)d_in[1];
    float4* out = (float4*)d_out;

    dim3 grid(BB * TT);   // 32768 rows
    dim3 block(128);
    patch_perm_kernel<<<grid, block>>>(x, perm, out);
}

// round 10
// speedup vs baseline: 1.0841x; 1.0041x over previous
#include <cuda_runtime.h>
#include <cstdint>

// PatchPermAugmentation: x (B,T,N,C)=(32,1024,512,3) fp32, perm (B, NB=512) int32.
// out[b,t,n,0] = x[b, perm[b,t/2]*2 + t%2, n, 0]; out[b,t,n,1:] = x[b,t,n,1:].
//
// FINAL (R1, measured optimum over 5 structural variants): one CTA per (b,t)
// row, 128 threads x 3 front-batched float4, fire-and-exit, default cache
// policies. 55.65us kernel @ 6.28 TB/s (78.5% of HBM spec) — DRAM-bound at
// the machine's streaming ceiling for this access pattern.
//
// Row view: for float index f within the contiguous 1536-float row, channel
// = f%3, and the gathered ch0 value lives at the SAME index f in the source
// row: out_row[f] = (f%3==0) ? src_row[f] : id_row[f]. Vectorized as
// per-component selects on float4 (period 3 in vec4 units:
// m==0 -> {x,w} from src; m==1 -> {z}; m==2 -> {y}).
// Identity rows (majority, selection rate 0.25) are a pure vectorized copy.
//
// Probed and rejected (all regressed):
//  R2  __stcs stores        56.6us  (loses cross-replay L2 carryover)
//  R3  persistent 2048 CTAs 62.7us  (loop-carried scoreboards kill MLP)
//  R5  reg cap / occ 82%    59.8us  (cold-path spills; occ not the limiter)
//  R7  __ldcs src loads     56.4us  (worse regalloc + evicts carryover lines)

#define BB 32
#define TT 1024
#define NN 512
#define PSZ 2
#define NBLK (TT / PSZ)            // 512
#define ROW_VEC4 ((NN * 3) / 4)    // 384

__global__ __launch_bounds__(128)
void patch_perm_kernel(const float4* __restrict__ x,
                       const int* __restrict__ perm,
                       float4* __restrict__ out) {
    const int row = blockIdx.x;          // b*T + t
    const int b = row >> 10;             // row / 1024
    const int t = row & (TT - 1);        // row % 1024
    const int blk = t >> 1;
    const int src_t = perm[b * NBLK + blk] * PSZ + (t & 1);

    const float4* __restrict__ idr = x + (size_t)row * ROW_VEC4;
    float4* __restrict__ outr = out + (size_t)row * ROW_VEC4;

    const int i0 = threadIdx.x;          // 0..127
    const int i1 = i0 + 128;
    const int i2 = i0 + 256;

    // Front-batched identity loads (MLP>=3)
    float4 v0 = idr[i0];
    float4 v1 = idr[i1];
    float4 v2 = idr[i2];

    if (src_t != t) {                    // uniform branch per CTA
        const float4* __restrict__ sr =
            x + (size_t)(b * TT + src_t) * ROW_VEC4;
        float4 s0 = sr[i0];
        float4 s1 = sr[i1];
        float4 s2 = sr[i2];

        // component selection by (float4 index) % 3
        int m0 = i0 % 3;
        if (m0 == 0)      { v0.x = s0.x; v0.w = s0.w; }
        else if (m0 == 1) { v0.z = s0.z; }
        else              { v0.y = s0.y; }

        int m1 = i1 % 3;
        if (m1 == 0)      { v1.x = s1.x; v1.w = s1.w; }
        else if (m1 == 1) { v1.z = s1.z; }
        else              { v1.y = s1.y; }

        int m2 = i2 % 3;
        if (m2 == 0)      { v2.x = s2.x; v2.w = s2.w; }
        else if (m2 == 1) { v2.z = s2.z; }
        else              { v2.y = s2.y; }
    }

    outr[i0] = v0;
    outr[i1] = v1;
    outr[i2] = v2;
}

extern "C" void kernel_launch(void* const* d_in, const int* in_sizes, int n_in,
                              void* d_out, int out_size) {
    const float4* x = (const float4*)d_in[0];
    const int* perm = (const int*)d_in[1];
    float4* out = (float4*)d_out;

    dim3 grid(BB * TT);   // 32768 rows
    dim3 block(128);
    patch_perm_kernel<<<grid, block>>>(x, perm, out);
}

// round 11
// speedup vs baseline: 1.0992x; 1.0139x over previous
#include <cuda_runtime.h>
#include <cstdint>

// PatchPermAugmentation: x (B,T,N,C)=(32,1024,512,3) fp32, perm (B, NB=512) int32.
// out[b,t,n,0] = x[b, perm[b,t/2]*2 + t%2, n, 0]; out[b,t,n,1:] = x[b,t,n,1:].
//
// R10 isolation experiment: R2's block-pairing WITHOUT __stcs (R2 bundled
// both; R7 showed cache hints alone cost ~0.7us). One CTA per patch block
// (b, blk): rows t=2*blk, 2*blk+1 share one perm entry and form 768
// contiguous float4. 256 threads x 3 front-batched float4, fire-and-exit,
// default cache policies everywhere.
//
// Identity blocks (majority, selection rate 0.25) are a pure vectorized
// copy. Permuted blocks also read the contiguous source block (L2-resident
// within the 6MB batch slab) and select components by (float4 index) % 3:
//   m==0 -> {x,w} from src; m==1 -> {z}; m==2 -> {y}.
//
// Ledger: R1 55.65us (baseline best, re-confirmed 56.8 +/- variance),
// R2 pair+__stcs 56.6, R3 persistent 62.7, R5 regcap 59.8, R7 __ldcs 56.4.

#define BB 32
#define TT 1024
#define NN 512
#define PSZ 2
#define NBLK (TT / PSZ)                 // 512
#define ROW_VEC4 ((NN * 3) / 4)         // 384
#define BLK_VEC4 (PSZ * ROW_VEC4)       // 768

__global__ __launch_bounds__(256)
void patch_perm_kernel(const float4* __restrict__ x,
                       const int* __restrict__ perm,
                       float4* __restrict__ out) {
    const int gblk = blockIdx.x;               // b*NBLK + blk, 0..16383
    const int blk = gblk & (NBLK - 1);
    const int src_blk = perm[gblk];            // perm is (B, NBLK) contiguous

    const size_t base = (size_t)gblk * BLK_VEC4;
    const float4* __restrict__ idr = x + base;
    float4* __restrict__ outr = out + base;

    const int i0 = threadIdx.x;                // 0..255
    const int i1 = i0 + 256;
    const int i2 = i0 + 512;

    // Front-batched identity loads (MLP >= 3)
    float4 v0 = idr[i0];
    float4 v1 = idr[i1];
    float4 v2 = idr[i2];

    if (src_blk != blk) {                      // uniform branch per CTA
        const float4* __restrict__ sr =
            x + ((size_t)(gblk - blk) + src_blk) * BLK_VEC4;
        float4 s0 = sr[i0];
        float4 s1 = sr[i1];
        float4 s2 = sr[i2];

        int m0 = i0 % 3;
        if (m0 == 0)      { v0.x = s0.x; v0.w = s0.w; }
        else if (m0 == 1) { v0.z = s0.z; }
        else              { v0.y = s0.y; }

        int m1 = i1 % 3;
        if (m1 == 0)      { v1.x = s1.x; v1.w = s1.w; }
        else if (m1 == 1) { v1.z = s1.z; }
        else              { v1.y = s1.y; }

        int m2 = i2 % 3;
        if (m2 == 0)      { v2.x = s2.x; v2.w = s2.w; }
        else if (m2 == 1) { v2.z = s2.z; }
        else              { v2.y = s2.y; }
    }

    outr[i0] = v0;
    outr[i1] = v1;
    outr[i2] = v2;
}

extern "C" void kernel_launch(void* const* d_in, const int* in_sizes, int n_in,
                              void* d_out, int out_size) {
    const float4* x = (const float4*)d_in[0];
    const int* perm = (const int*)d_in[1];
    float4* out = (float4*)d_out;

    dim3 grid(BB * NBLK);   // 16384 patch blocks
    dim3 block(256);
    patch_perm_kernel<<<grid, block>>>(x, perm, out);
}